// round 4
// baseline (speedup 1.0000x reference)
#include <cuda_runtime.h>
#include <cuda_fp16.h>

// Problem constants (fixed by the dataset)
#define S_ 16384
#define N_ 2048
#define C_ 8
#define PAD 32                      // zero padding each side (halves); |floor(shift)| <= ~15
#define ROW (N_ + 2 * PAD)          // 2112 halves per component row
#define ROWW (ROW / 2)              // 1056 words (half2) per row
#define TOTW (C_ * ROWW)            // 8448 words per parity copy
#define SMEM_BYTES (2 * TOTW * 4)   // E + O copies = 67584 B (same as one fp32 copy)

#define NTHREADS 512
#define NBLOCKS 296                 // 2 CTAs/SM * 148 SMs
#define WARPS_PER_CTA (NTHREADS / 32)
#define NWARPS (NBLOCKS * WARPS_PER_CTA)   // 4736

#define GROUPS (S_ / 32)            // 512 sample-groups of 32 (one per lane)
#define CHUNK_COLS 32               // columns per task
#define CHUNKS (N_ / CHUNK_COLS)    // 64
#define NTASKS (GROUPS * CHUNKS)    // 32768 -> 6.92 tasks/warp, 1.2% tail

extern __shared__ unsigned smemw[];   // [2*TOTW] words: E copy then O copy (O[i]=E[i+1 half])

__global__ __launch_bounds__(NTHREADS, 2)
void smf_shift_kernel(const float* __restrict__ components,
                      const float* __restrict__ contributions,
                      const float* __restrict__ shift,
                      float* __restrict__ out)
{
    // ---- Stage 1: zero E copy (covers pads) ----
    for (int i = threadIdx.x; i < TOTW; i += NTHREADS) smemw[i] = 0u;
    __syncthreads();

    // ---- Stage 2: fp32 -> fp16, write E copy ----
    {
        const float4* src = reinterpret_cast<const float4*>(components);
        __half2* e2 = reinterpret_cast<__half2*>(smemw);
        for (int i = threadIdx.x; i < C_ * N_ / 4; i += NTHREADS) {
            int c = i >> 9;               // / (N_/4)
            int j = i & 511;              // % (N_/4)
            float4 v = __ldg(src + i);
            unsigned wi = c * ROWW + PAD / 2 + 2 * j;   // PAD even, aligned
            e2[wi]     = __floats2half2_rn(v.x, v.y);
            e2[wi + 1] = __floats2half2_rn(v.z, v.w);
        }
    }
    __syncthreads();

    // ---- Stage 3: build odd-parity copy O[i] = halves (E[2i+1], E[2i+2]) ----
    for (int i = threadIdx.x; i < TOTW; i += NTHREADS) {
        unsigned a = smemw[i];
        unsigned b = (i + 1 < TOTW) ? smemw[i + 1] : 0u;
        smemw[TOTW + i] = __byte_perm(a, b, 0x5432);
    }
    __syncthreads();

    const __half2* h2 = reinterpret_cast<const __half2*>(smemw);

    const int lane = threadIdx.x & 31;
    const int wid  = threadIdx.x >> 5;
    const int wg   = blockIdx.x * WARPS_PER_CTA + wid;

    for (int task = wg; task < NTASKS; task += NWARPS) {
        const int group = task >> 6;           // / CHUNKS
        const int chunk = task & (CHUNKS - 1);
        const int s  = group * 32 + lane;      // lane <-> sample
        const int n0 = chunk * CHUNK_COLS;

        // ---- Per-(s,c): integer shift d, weights, parity-resolved word ptr ----
        const float4* shp = reinterpret_cast<const float4*>(shift + (size_t)s * C_);
        const float4* ctp = reinterpret_cast<const float4*>(contributions + (size_t)s * C_);
        float4 sh0 = __ldg(shp), sh1 = __ldg(shp + 1);
        float4 ct0 = __ldg(ctp), ct1 = __ldg(ctp + 1);
        float shv[8] = {sh0.x, sh0.y, sh0.z, sh0.w, sh1.x, sh1.y, sh1.z, sh1.w};
        float ctv[8] = {ct0.x, ct0.y, ct0.z, ct0.w, ct1.x, ct1.y, ct1.z, ct1.w};

        int   wp[8];
        float a0[8], a1[8], w0v[8], w1v[8];
        #pragma unroll
        for (int c = 0; c < 8; c++) {
            float sv = shv[c];
            float fl = floorf(sv);
            float f  = sv - fl;
            int d = (int)fl;
            d = max(-PAD, min(PAD - 2, d));    // memory-safety clamp (never hit by data)
            w0v[c] = ctv[c] * (1.0f - f);
            w1v[c] = ctv[c] * f;
            int B = PAD + d + n0;              // half index of tap v_0
            int p = B & 1;
            wp[c] = p * TOTW + c * ROWW + (B >> 1);
            __half2 h = h2[wp[c]];             // word q: (v_0, v_1)
            a0[c] = __low2float(h);
            a1[c] = __high2float(h);
        }

        float* optr = out + (size_t)s * N_ + n0;

        #pragma unroll 1
        for (int k8 = 0; k8 < CHUNK_COLS; k8 += 8) {
            float acc[8];
            #pragma unroll
            for (int t = 0; t < 4; t++) {       // 4 pair-steps = 8 outputs
                float s0 = 0.0f, s1 = 0.0f;
                #pragma unroll
                for (int c = 0; c < 8; c++) {
                    __half2 h = h2[wp[c] + t + 1];   // next word: (v_{2t+2}, v_{2t+3})
                    float b0 = __low2float(h);
                    float b1 = __high2float(h);
                    s0 = fmaf(w0v[c], a0[c], s0);
                    s0 = fmaf(w1v[c], a1[c], s0);
                    s1 = fmaf(w0v[c], a1[c], s1);
                    s1 = fmaf(w1v[c], b0, s1);
                    a0[c] = b0;
                    a1[c] = b1;
                }
                acc[2 * t]     = s0;
                acc[2 * t + 1] = s1;
            }
            #pragma unroll
            for (int c = 0; c < 8; c++) wp[c] += 4;

            // 32B contiguous per lane -> full-sector writes
            float4* o = reinterpret_cast<float4*>(optr + k8);
            o[0] = make_float4(acc[0], acc[1], acc[2], acc[3]);
            o[1] = make_float4(acc[4], acc[5], acc[6], acc[7]);
        }
    }
}

extern "C" void kernel_launch(void* const* d_in, const int* in_sizes, int n_in,
                              void* d_out, int out_size)
{
    // metadata order: inputs (unused), components, contributions, shift
    const float* components    = (const float*)d_in[1];
    const float* contributions = (const float*)d_in[2];
    const float* shift         = (const float*)d_in[3];
    float* out = (float*)d_out;

    cudaFuncSetAttribute(smf_shift_kernel,
                         cudaFuncAttributeMaxDynamicSharedMemorySize, SMEM_BYTES);

    smf_shift_kernel<<<NBLOCKS, NTHREADS, SMEM_BYTES>>>(
        components, contributions, shift, out);
}

// round 5
// speedup vs baseline: 1.0112x; 1.0112x over previous
#include <cuda_runtime.h>
#include <cuda_fp16.h>

// Problem constants (fixed by the dataset)
#define S_ 16384
#define N_ 2048
#define C_ 8
#define PAD 32                      // zero padding each side (halves); |floor(shift)| <= ~15
#define ROW (N_ + 2 * PAD)          // 2112 halves per component row
#define ROWW (ROW / 2)              // 1056 words (half2) per row
#define TOTW (C_ * ROWW)            // 8448 words per parity copy
#define SMEM_BYTES (2 * TOTW * 4)   // E + O copies = 67584 B (same as one fp32 copy)

#define NTHREADS 512
#define NBLOCKS 296                 // 2 CTAs/SM * 148 SMs
#define WARPS_PER_CTA (NTHREADS / 32)
#define NWARPS (NBLOCKS * WARPS_PER_CTA)   // 4736

#define GROUPS (S_ / 32)            // 512 sample-groups of 32 (one per lane)
#define CHUNK_COLS 32               // columns per task
#define CHUNKS (N_ / CHUNK_COLS)    // 64
#define NTASKS (GROUPS * CHUNKS)    // 32768 -> 6.92 tasks/warp, 1.2% tail

extern __shared__ unsigned smemw[];   // [2*TOTW] words: E copy then O copy (O[i]=E[i+1 half])

__global__ __launch_bounds__(NTHREADS, 2)
void smf_shift_kernel(const float* __restrict__ components,
                      const float* __restrict__ contributions,
                      const float* __restrict__ shift,
                      float* __restrict__ out)
{
    // ---- Stage 1: zero E copy (covers pads) ----
    for (int i = threadIdx.x; i < TOTW; i += NTHREADS) smemw[i] = 0u;
    __syncthreads();

    // ---- Stage 2: fp32 -> fp16, write E copy ----
    {
        const float4* src = reinterpret_cast<const float4*>(components);
        __half2* e2 = reinterpret_cast<__half2*>(smemw);
        for (int i = threadIdx.x; i < C_ * N_ / 4; i += NTHREADS) {
            int c = i >> 9;               // / (N_/4)
            int j = i & 511;              // % (N_/4)
            float4 v = __ldg(src + i);
            unsigned wi = c * ROWW + PAD / 2 + 2 * j;   // PAD even, aligned
            e2[wi]     = __floats2half2_rn(v.x, v.y);
            e2[wi + 1] = __floats2half2_rn(v.z, v.w);
        }
    }
    __syncthreads();

    // ---- Stage 3: build odd-parity copy O[i] = halves (E[2i+1], E[2i+2]) ----
    for (int i = threadIdx.x; i < TOTW; i += NTHREADS) {
        unsigned a = smemw[i];
        unsigned b = (i + 1 < TOTW) ? smemw[i + 1] : 0u;
        smemw[TOTW + i] = __byte_perm(a, b, 0x5432);
    }
    __syncthreads();

    const __half2* h2 = reinterpret_cast<const __half2*>(smemw);

    const int lane = threadIdx.x & 31;
    const int wid  = threadIdx.x >> 5;
    const int wg   = blockIdx.x * WARPS_PER_CTA + wid;

    for (int task = wg; task < NTASKS; task += NWARPS) {
        const int group = task >> 6;           // / CHUNKS
        const int chunk = task & (CHUNKS - 1);
        const int s  = group * 32 + lane;      // lane <-> sample
        const int n0 = chunk * CHUNK_COLS;

        // ---- Per-(s,c): integer shift d, weights, parity-resolved word ptr ----
        const float4* shp = reinterpret_cast<const float4*>(shift + (size_t)s * C_);
        const float4* ctp = reinterpret_cast<const float4*>(contributions + (size_t)s * C_);
        float4 sh0 = __ldg(shp), sh1 = __ldg(shp + 1);
        float4 ct0 = __ldg(ctp), ct1 = __ldg(ctp + 1);
        float shv[8] = {sh0.x, sh0.y, sh0.z, sh0.w, sh1.x, sh1.y, sh1.z, sh1.w};
        float ctv[8] = {ct0.x, ct0.y, ct0.z, ct0.w, ct1.x, ct1.y, ct1.z, ct1.w};

        int   wp[8];
        float a0[8], a1[8], w0v[8], w1v[8];
        #pragma unroll
        for (int c = 0; c < 8; c++) {
            float sv = shv[c];
            float fl = floorf(sv);
            float f  = sv - fl;
            int d = (int)fl;
            d = max(-PAD, min(PAD - 2, d));    // memory-safety clamp (never hit by data)
            w0v[c] = ctv[c] * (1.0f - f);
            w1v[c] = ctv[c] * f;
            int B = PAD + d + n0;              // half index of tap v_0
            int p = B & 1;
            wp[c] = p * TOTW + c * ROWW + (B >> 1);
            __half2 h = h2[wp[c]];             // word q: (v_0, v_1)
            a0[c] = __low2float(h);
            a1[c] = __high2float(h);
        }

        float* optr = out + (size_t)s * N_ + n0;

        #pragma unroll 1
        for (int k8 = 0; k8 < CHUNK_COLS; k8 += 8) {
            float acc[8];
            #pragma unroll
            for (int t = 0; t < 4; t++) {       // 4 pair-steps = 8 outputs
                float s0 = 0.0f, s1 = 0.0f;
                #pragma unroll
                for (int c = 0; c < 8; c++) {
                    __half2 h = h2[wp[c] + t + 1];   // next word: (v_{2t+2}, v_{2t+3})
                    float b0 = __low2float(h);
                    float b1 = __high2float(h);
                    s0 = fmaf(w0v[c], a0[c], s0);
                    s0 = fmaf(w1v[c], a1[c], s0);
                    s1 = fmaf(w0v[c], a1[c], s1);
                    s1 = fmaf(w1v[c], b0, s1);
                    a0[c] = b0;
                    a1[c] = b1;
                }
                acc[2 * t]     = s0;
                acc[2 * t + 1] = s1;
            }
            #pragma unroll
            for (int c = 0; c < 8; c++) wp[c] += 4;

            // 32B contiguous per lane -> full-sector writes
            float4* o = reinterpret_cast<float4*>(optr + k8);
            o[0] = make_float4(acc[0], acc[1], acc[2], acc[3]);
            o[1] = make_float4(acc[4], acc[5], acc[6], acc[7]);
        }
    }
}

extern "C" void kernel_launch(void* const* d_in, const int* in_sizes, int n_in,
                              void* d_out, int out_size)
{
    // metadata order: inputs (unused), components, contributions, shift
    const float* components    = (const float*)d_in[1];
    const float* contributions = (const float*)d_in[2];
    const float* shift         = (const float*)d_in[3];
    float* out = (float*)d_out;

    cudaFuncSetAttribute(smf_shift_kernel,
                         cudaFuncAttributeMaxDynamicSharedMemorySize, SMEM_BYTES);

    smf_shift_kernel<<<NBLOCKS, NTHREADS, SMEM_BYTES>>>(
        components, contributions, shift, out);
}

// round 6
// speedup vs baseline: 1.0116x; 1.0004x over previous
#include <cuda_runtime.h>
#include <cuda_fp16.h>

// Problem constants (fixed by the dataset)
#define S_ 16384
#define N_ 2048
#define C_ 8
#define PAD 32                      // zero padding each side (halves); |floor(shift)| <= ~15
#define ROW (N_ + 2 * PAD)          // 2112 halves per component row
#define ROWW (ROW / 2)              // 1056 words (half2) per row
#define TOTW (C_ * ROWW)            // 8448 words per parity copy
#define SMEM_BYTES (2 * TOTW * 4)   // E + O copies = 67584 B (same as one fp32 copy)

#define NTHREADS 512
#define NBLOCKS 296                 // 2 CTAs/SM * 148 SMs
#define WARPS_PER_CTA (NTHREADS / 32)
#define NWARPS (NBLOCKS * WARPS_PER_CTA)   // 4736

#define GROUPS (S_ / 32)            // 512 sample-groups of 32 (one per lane)
#define CHUNK_COLS 32               // columns per task
#define CHUNKS (N_ / CHUNK_COLS)    // 64
#define NTASKS (GROUPS * CHUNKS)    // 32768 -> 6.92 tasks/warp, 1.2% tail

extern __shared__ unsigned smemw[];   // [2*TOTW] words: E copy then O copy (O[i]=E[i+1 half])

__global__ __launch_bounds__(NTHREADS, 2)
void smf_shift_kernel(const float* __restrict__ components,
                      const float* __restrict__ contributions,
                      const float* __restrict__ shift,
                      float* __restrict__ out)
{
    // ---- Stage 1: zero E copy (covers pads) ----
    for (int i = threadIdx.x; i < TOTW; i += NTHREADS) smemw[i] = 0u;
    __syncthreads();

    // ---- Stage 2: fp32 -> fp16, write E copy ----
    {
        const float4* src = reinterpret_cast<const float4*>(components);
        __half2* e2 = reinterpret_cast<__half2*>(smemw);
        for (int i = threadIdx.x; i < C_ * N_ / 4; i += NTHREADS) {
            int c = i >> 9;               // / (N_/4)
            int j = i & 511;              // % (N_/4)
            float4 v = __ldg(src + i);
            unsigned wi = c * ROWW + PAD / 2 + 2 * j;   // PAD even, aligned
            e2[wi]     = __floats2half2_rn(v.x, v.y);
            e2[wi + 1] = __floats2half2_rn(v.z, v.w);
        }
    }
    __syncthreads();

    // ---- Stage 3: build odd-parity copy O[i] = halves (E[2i+1], E[2i+2]) ----
    for (int i = threadIdx.x; i < TOTW; i += NTHREADS) {
        unsigned a = smemw[i];
        unsigned b = (i + 1 < TOTW) ? smemw[i + 1] : 0u;
        smemw[TOTW + i] = __byte_perm(a, b, 0x5432);
    }
    __syncthreads();

    const __half2* h2 = reinterpret_cast<const __half2*>(smemw);

    const int lane = threadIdx.x & 31;
    const int wid  = threadIdx.x >> 5;
    const int wg   = blockIdx.x * WARPS_PER_CTA + wid;

    for (int task = wg; task < NTASKS; task += NWARPS) {
        const int group = task >> 6;           // / CHUNKS
        const int chunk = task & (CHUNKS - 1);
        const int s  = group * 32 + lane;      // lane <-> sample
        const int n0 = chunk * CHUNK_COLS;

        // ---- Per-(s,c): integer shift d, weights, parity-resolved word ptr ----
        const float4* shp = reinterpret_cast<const float4*>(shift + (size_t)s * C_);
        const float4* ctp = reinterpret_cast<const float4*>(contributions + (size_t)s * C_);
        float4 sh0 = __ldg(shp), sh1 = __ldg(shp + 1);
        float4 ct0 = __ldg(ctp), ct1 = __ldg(ctp + 1);
        float shv[8] = {sh0.x, sh0.y, sh0.z, sh0.w, sh1.x, sh1.y, sh1.z, sh1.w};
        float ctv[8] = {ct0.x, ct0.y, ct0.z, ct0.w, ct1.x, ct1.y, ct1.z, ct1.w};

        int   wp[8];
        float a0[8], a1[8], w0v[8], w1v[8];
        #pragma unroll
        for (int c = 0; c < 8; c++) {
            float sv = shv[c];
            float fl = floorf(sv);
            float f  = sv - fl;
            int d = (int)fl;
            d = max(-PAD, min(PAD - 2, d));    // memory-safety clamp (never hit by data)
            w0v[c] = ctv[c] * (1.0f - f);
            w1v[c] = ctv[c] * f;
            int B = PAD + d + n0;              // half index of tap v_0
            int p = B & 1;
            wp[c] = p * TOTW + c * ROWW + (B >> 1);
            __half2 h = h2[wp[c]];             // word q: (v_0, v_1)
            a0[c] = __low2float(h);
            a1[c] = __high2float(h);
        }

        float* optr = out + (size_t)s * N_ + n0;

        #pragma unroll 1
        for (int k8 = 0; k8 < CHUNK_COLS; k8 += 8) {
            float acc[8];
            #pragma unroll
            for (int t = 0; t < 4; t++) {       // 4 pair-steps = 8 outputs
                float s0 = 0.0f, s1 = 0.0f;
                #pragma unroll
                for (int c = 0; c < 8; c++) {
                    __half2 h = h2[wp[c] + t + 1];   // next word: (v_{2t+2}, v_{2t+3})
                    float b0 = __low2float(h);
                    float b1 = __high2float(h);
                    s0 = fmaf(w0v[c], a0[c], s0);
                    s0 = fmaf(w1v[c], a1[c], s0);
                    s1 = fmaf(w0v[c], a1[c], s1);
                    s1 = fmaf(w1v[c], b0, s1);
                    a0[c] = b0;
                    a1[c] = b1;
                }
                acc[2 * t]     = s0;
                acc[2 * t + 1] = s1;
            }
            #pragma unroll
            for (int c = 0; c < 8; c++) wp[c] += 4;

            // 32B contiguous per lane -> full-sector writes
            float4* o = reinterpret_cast<float4*>(optr + k8);
            o[0] = make_float4(acc[0], acc[1], acc[2], acc[3]);
            o[1] = make_float4(acc[4], acc[5], acc[6], acc[7]);
        }
    }
}

extern "C" void kernel_launch(void* const* d_in, const int* in_sizes, int n_in,
                              void* d_out, int out_size)
{
    // metadata order: inputs (unused), components, contributions, shift
    const float* components    = (const float*)d_in[1];
    const float* contributions = (const float*)d_in[2];
    const float* shift         = (const float*)d_in[3];
    float* out = (float*)d_out;

    cudaFuncSetAttribute(smf_shift_kernel,
                         cudaFuncAttributeMaxDynamicSharedMemorySize, SMEM_BYTES);

    smf_shift_kernel<<<NBLOCKS, NTHREADS, SMEM_BYTES>>>(
        components, contributions, shift, out);
}